// round 9
// baseline (speedup 1.0000x reference)
#include <cuda_runtime.h>

// MultiScaleEdgeBuilder: B=64 graphs, 256 nodes each, all ordered intra-graph
// pairs (i != j). Output (float32, concatenated):
//   [0, 2E)    edge_index  (row indices, then col indices)
//   [2E, 18E)  edge_attr   (zeros, EDGE_DIM=16)
//   [18E, 21E) rbf         exp(-d^2 / c^2), c in {4, 8, 12}
// E = 64 * 256 * 255 = 4,177,920.
//
// R8: stream-purity test. Split into two launches so the DRAM controller
// sees (1) a small 3-stream compute kernel (95 MB: idx + rbf) and (2) one
// pure linear memset sweep (256 MB zeros) instead of a 4-stream braid.
// Pure memset is DRAM's best-efficiency pattern; zeros are 73% of bytes.

#define NPER    256
#define EPG     (NPER * (NPER - 1))      // 65280 edges per graph
#define E_TOTAL (64 * EPG)               // 4,177,920 = 8160 * 512
#define EPB     512                      // edges per block
#define NTHR    512

// ---- kernel 1: edge_index + rbf (95 MB of writes) -----------------------
__global__ __launch_bounds__(NTHR, 4)
void msed_compute_kernel(const float* __restrict__ pos,
                         float* __restrict__ out) {
    __shared__ __align__(16) float s_rbf[3 * EPB];   // 6 KB

    const int tid = threadIdx.x;
    const int e0  = blockIdx.x * EPB;        // first edge of this block
    const int e   = e0 + tid;

    // decompose edge id -> (g, i, j)
    int g  = e / EPG;                        // const-div -> mul.hi
    int r  = e - g * EPG;
    int i  = r / 255;
    int jp = r - i * 255;
    int j  = jp + (jp >= i);                 // skip diagonal

    int row = (g << 8) + i;
    int col = (g << 8) + j;

    // edge_index: consecutive e -> perfectly coalesced
    out[e]           = (float)row;
    out[E_TOTAL + e] = (float)col;

    // rbf: exp(-d^2/c^2), no sqrt needed
    const float* pr = pos + 3 * row;         // warp-mostly-uniform, L1/L2 hit
    const float* pc = pos + 3 * col;
    float dx = pr[0] - pc[0];
    float dy = pr[1] - pc[1];
    float dz = pr[2] - pc[2];
    float d2 = dx * dx + dy * dy + dz * dz;

    // stride-3 smem writes: gcd(3,32)=1 -> bank-conflict-free
    s_rbf[3 * tid + 0] = __expf(-d2 * (1.0f / 16.0f));   // c = 4
    s_rbf[3 * tid + 1] = __expf(-d2 * (1.0f / 64.0f));   // c = 8
    s_rbf[3 * tid + 2] = __expf(-d2 * (1.0f / 144.0f));  // c = 12

    __syncthreads();

    // rbf out: 1536 floats = 384 float4, coalesced from smem
    if (tid < 384) {
        const float4* s4 = (const float4*)s_rbf;
        float4* rp = (float4*)(out + 18 * E_TOTAL + 3 * e0);
        rp[tid] = s4[tid];
    }
}

// ---- kernel 2: pure linear zero sweep (256 MB) --------------------------
// 16*E floats = 16,711,680 float4 = 8160 blocks * 512 threads * 4 each.
__global__ __launch_bounds__(NTHR, 4)
void msed_zero_kernel(float* __restrict__ out) {
    const int tid = threadIdx.x;
    float4* zp = (float4*)(out + 2 * E_TOTAL) + blockIdx.x * (NTHR * 4);
    float4 z = make_float4(0.f, 0.f, 0.f, 0.f);
    #pragma unroll
    for (int k = 0; k < 4; k++)
        zp[tid + NTHR * k] = z;              // contiguous 32 KB per block
}

extern "C" void kernel_launch(void* const* d_in, const int* in_sizes, int n_in,
                              void* d_out, int out_size) {
    const float* pos = (const float*)d_in[0];   // [16384, 3] float32
    float* out = (float*)d_out;                 // 21 * E floats

    msed_compute_kernel<<<E_TOTAL / EPB, NTHR>>>(pos, out);
    msed_zero_kernel<<<E_TOTAL / EPB, NTHR>>>(out);
}

// round 11
// speedup vs baseline: 1.1873x; 1.1873x over previous
#include <cuda_runtime.h>

// MultiScaleEdgeBuilder: B=64 graphs, 256 nodes each, all ordered intra-graph
// pairs (i != j). Output (float32, concatenated):
//   [0, 2E)    edge_index  (row indices, then col indices)
//   [2E, 18E)  edge_attr   (zeros, EDGE_DIM=16)
//   [18E, 21E) rbf         exp(-d^2 / c^2), c in {4, 8, 12}
// E = 64 * 256 * 255 = 4,177,920.
//
// R9 (FINAL = R7/R5 config): single fused pass. Evidence across R2-R8:
//   - bench period pinned at 51.7us = 351MB / 6.79TB/s = ~85% of spec HBM
//     (the sustained write ceiling); all perturbations landed within 0.15%.
//   - fused zeros are free overlap under the __expf chains; splitting them
//     out (R8) made compute latency-bound and regressed 18%.
//   - __stcs regressed (L2 is the write-combining buffer); evict-normal wins.
//   - all four store regions fully coalesced; rbf staged via smem (stride-3
//     writes are bank-conflict-free), zeros as contiguous float4.

#define NPER    256
#define EPG     (NPER * (NPER - 1))      // 65280 edges per graph
#define E_TOTAL (64 * EPG)               // 4,177,920 = 8160 * 512
#define EPB     512                      // edges per block
#define NTHR    512

__global__ __launch_bounds__(NTHR, 4)
void MultiScaleEdgeBuilder_kernel(const float* __restrict__ pos,
                                  float* __restrict__ out) {
    __shared__ __align__(16) float s_rbf[3 * EPB];   // 6 KB

    const int tid = threadIdx.x;
    const int e0  = blockIdx.x * EPB;        // first edge of this block
    const int e   = e0 + tid;

    // ---- zeros first: 512*16 floats = 2048 float4, contiguous 32 KB -----
    // Dependency-free stores: saturate the store pipe / DRAM while the
    // rbf chain (loads + MUFU) is in flight. This overlap is load-bearing
    // (removing it in R8 cost 18%).
    {
        float4 z = make_float4(0.f, 0.f, 0.f, 0.f);
        float4* zp = (float4*)(out + 2 * E_TOTAL + 16 * e0);
        #pragma unroll
        for (int k = 0; k < 4; k++)
            zp[tid + NTHR * k] = z;          // coalesced 128B per warp-store
    }

    // ---- decompose edge id -> (g, i, j) ---------------------------------
    int g  = e / EPG;                        // const-div -> mul.hi
    int r  = e - g * EPG;
    int i  = r / 255;
    int jp = r - i * 255;
    int j  = jp + (jp >= i);                 // skip diagonal

    int row = (g << 8) + i;
    int col = (g << 8) + j;

    // ---- edge_index: consecutive e -> perfectly coalesced ---------------
    out[e]           = (float)row;
    out[E_TOTAL + e] = (float)col;

    // ---- rbf: exp(-d^2/c^2), no sqrt needed -----------------------------
    const float* pr = pos + 3 * row;         // warp-mostly-uniform, L1/L2 hit
    const float* pc = pos + 3 * col;
    float dx = pr[0] - pc[0];
    float dy = pr[1] - pc[1];
    float dz = pr[2] - pc[2];
    float d2 = dx * dx + dy * dy + dz * dz;

    s_rbf[3 * tid + 0] = __expf(-d2 * (1.0f / 16.0f));   // c = 4  (stride-3:
    s_rbf[3 * tid + 1] = __expf(-d2 * (1.0f / 64.0f));   //  c = 8  bank-
    s_rbf[3 * tid + 2] = __expf(-d2 * (1.0f / 144.0f));  //  c = 12 conflict-free)

    __syncthreads();

    // ---- rbf out: 1536 floats = 384 float4, coalesced from smem ---------
    if (tid < 384) {
        const float4* s4 = (const float4*)s_rbf;
        float4* rp = (float4*)(out + 18 * E_TOTAL + 3 * e0);
        rp[tid] = s4[tid];
    }
}

extern "C" void kernel_launch(void* const* d_in, const int* in_sizes, int n_in,
                              void* d_out, int out_size) {
    const float* pos = (const float*)d_in[0];   // [16384, 3] float32
    float* out = (float*)d_out;                 // 21 * E floats

    MultiScaleEdgeBuilder_kernel<<<E_TOTAL / EPB, NTHR>>>(pos, out);
}